// round 10
// baseline (speedup 1.0000x reference)
#include <cuda_runtime.h>
#include <cstdint>

// Fully fused Precoding-GNN, R10: R3-exact structure (proven 581us) with the
// edge-GEMM Ws weights moved to the CONSTANT bank, loaded as ulonglong2
// (LDC.128, zero repack -> same register shape as R3; avoids R8's spill).
// Constant port is separate from the smem crossbar -> ~4K wavefronts/layer
// leave the LSU. Upload path (prep kernel + symbol memcpy) proven in R8.
// One sample per 2-CTA cluster, hidden state resident in SMEM all 5 layers.
// BS=1024, M=64, K=32, D=32. Each CTA owns 32 antennas -> 1024 edges.
// h layout: h[d][e], e = m_loc*32 + k (pitch 1024 floats).

#define NT 512
#define NW 16

typedef unsigned long long ull;

// Transposed Ws: cws[wofs + d*32 + h] = Ws[h][d]; layer1 at 0, layers2-4 at l*1024
__constant__ __align__(16) float cws[4096];
__device__ float wstage[4096];

struct SM {
  float h[32 * 1024];      // 131072 B hidden state [d][e]
  float xs[2 * 1024];      //   8192 B layer-1 input [c][e]
  float wsT5[64];          //    256 B layer-5 Ws^T (stride 2)
  float wmT[1024];         //   4096 B Wm^T: wmT[d*32+h]
  float wkT[1024];         //   4096 B Wk^T
  float mm[32 * 34];       //   4352 B msg_m[m][d]      (pitch 34)
  float mkpL[2][32 * 34];  //   8704 B msg_k partial [k][d], parity buffered
  float mkc[32 * 34];      //   4352 B msg_k combined [k][d]
  float bm[32 * 34];       //   4352 B Wm@msg_m  [m][h]
  float bk[32 * 34];       //   4352 B Wk@msg_k  [k][h]
  float red[NW];
  float powslot;
};

struct Params {
  const float* x;
  const float* w[15];
  float* out;
};

extern __shared__ __align__(16) char smem_raw[];

__device__ __forceinline__ uint32_t s2u(const void* p) {
  uint32_t a;
  asm("{ .reg .u64 t; cvta.to.shared.u64 t, %1; cvt.u32.u64 %0, t; }"
      : "=r"(a) : "l"(p));
  return a;
}
__device__ __forceinline__ float peer_ldf(const float* p, uint32_t peer) {
  uint32_t ra;
  asm("mapa.shared::cluster.u32 %0, %1, %2;" : "=r"(ra) : "r"(s2u(p)), "r"(peer));
  float v;
  asm volatile("ld.shared::cluster.f32 %0, [%1];" : "=f"(v) : "r"(ra));
  return v;
}
__device__ __forceinline__ float2 peer_ldf2(const float* p, uint32_t peer) {
  uint32_t ra;
  asm("mapa.shared::cluster.u32 %0, %1, %2;" : "=r"(ra) : "r"(s2u(p)), "r"(peer));
  float2 v;
  asm volatile("ld.shared::cluster.v2.f32 {%0,%1}, [%2];"
               : "=f"(v.x), "=f"(v.y) : "r"(ra));
  return v;
}
__device__ __forceinline__ void csync() {
  asm volatile("barrier.cluster.arrive.aligned;" ::: "memory");
  asm volatile("barrier.cluster.wait.aligned;" ::: "memory");
}
__device__ __forceinline__ ull pk2(float x, float y) {
  ull r; asm("mov.b64 %0,{%1,%2};" : "=l"(r) : "f"(x), "f"(y)); return r;
}
__device__ __forceinline__ void upk2(ull v, float& x, float& y) {
  asm("mov.b64 {%0,%1},%2;" : "=f"(x), "=f"(y) : "l"(v));
}
__device__ __forceinline__ void fma2(ull& d, ull a, ull b) {
  asm("fma.rn.f32x2 %0,%1,%2,%0;" : "+l"(d) : "l"(a), "l"(b));
}

// ---- prep: transpose Ws (layers 1-4) into wstage for the constant copy ----
__global__ void prep_kernel(const float* w1, const float* w2, const float* w3,
                            const float* w4) {
  int t = threadIdx.x;
  if (t < 64) {  // layer 1, DIN=2: wstage[d*32+h] = w1[h*2+d]
    int d = t >> 5, hh = t & 31;
    wstage[d * 32 + hh] = w1[hh * 2 + d];
  }
  const float* ws[3] = {w2, w3, w4};
#pragma unroll
  for (int l = 0; l < 3; l++)
    for (int i = t; i < 1024; i += NT) {
      int d = i >> 5, hh = i & 31;
      wstage[(l + 1) * 1024 + d * 32 + hh] = ws[l][hh * 32 + d];
    }
}

// msg_m[m][d] = sum_k src[d][m*32+k]  (contiguous float4 loads, shfl tree)
// mkp[k][d]  = sum_{m_loc} src[d][m*32+k]  (contiguous-lane, serial over m)
template <int DIN>
__device__ __forceinline__ void msgs(SM* s, const float* src, float* mkp,
                                     int lane, int wid) {
  for (int r = wid; r < DIN * 8; r += NW) {
    int d = r >> 3, g = r & 7;  // g: group of 4 antennas (128 floats)
    float4 v = *(const float4*)(src + d * 1024 + g * 128 + lane * 4);
    float t = v.x + v.y + v.z + v.w;
    t += __shfl_xor_sync(0xffffffffu, t, 1);
    t += __shfl_xor_sync(0xffffffffu, t, 2);
    t += __shfl_xor_sync(0xffffffffu, t, 4);
    if ((lane & 7) == 0) s->mm[(g * 4 + (lane >> 3)) * 34 + d] = t;
  }
  for (int d = wid; d < DIN; d += NW) {
    float t = 0.f;
#pragma unroll
    for (int m2 = 0; m2 < 32; m2++) t += src[d * 1024 + m2 * 32 + lane];
    mkp[lane * 34 + d] = t;
  }
}

// combine: mkc = mkp(local) + mkp(peer), float2 granularity
template <int DIN>
__device__ __forceinline__ void combine_mk(SM* s, const float* mkp, int tid,
                                           uint32_t peer) {
  constexpr int PAIRS = 32 * DIN / 2;
  for (int i = tid; i < PAIRS; i += NT) {
    int k = i / (DIN / 2), dp = i % (DIN / 2);
    int off = k * 34 + 2 * dp;
    float2 a = *(const float2*)(mkp + off);
    float2 b = peer_ldf2(mkp + off, peer);
    *(float2*)(s->mkc + off) = make_float2(a.x + b.x, a.y + b.y);
  }
}

// One GNN layer, DOUT=32, relu. src = xs (L1) or h (L2-4), dest = h in place.
// wofs: offset of this layer's transposed Ws inside cws.
template <int DIN>
__device__ __forceinline__ void layer32(SM* s, const float* src, int wofs,
                                        const float* gWm, const float* gWk,
                                        int par, int tid, int lane, int wid,
                                        uint32_t peer) {
  float* mkp = s->mkpL[par];
  // stage transposed Wm/Wk: wT[d*32 + h]  (Ws comes from the constant bank)
  for (int i = tid; i < DIN * 32; i += NT) {
    int d = i >> 5, hh = i & 31;
    s->wmT[i] = gWm[hh * DIN + d];
    s->wkT[i] = gWk[hh * DIN + d];
  }
  msgs<DIN>(s, src, mkp, lane, wid);
  csync();  // mkp visible cluster-wide; also orders local staging/mm
  combine_mk<DIN>(s, mkp, tid, peer);
  __syncthreads();
  // bias GEMMs (f32x2): bm[mk][h], bk[mk][h]; 512 threads, 1 slot each
  {
    const int jj = tid & 15, mk = tid >> 4;
    ull tb = 0, tk = 0;
#pragma unroll
    for (int d = 0; d < DIN; d++) {
      ull wmv = *(const ull*)(s->wmT + d * 32 + 2 * jj);
      ull wkv = *(const ull*)(s->wkT + d * 32 + 2 * jj);
      float am = s->mm[mk * 34 + d];
      float ak = s->mkc[mk * 34 + d];
      fma2(tb, pk2(am, am), wmv);
      fma2(tk, pk2(ak, ak), wkv);
    }
    float a, b;
    upk2(tb, a, b); *(float2*)(s->bm + mk * 34 + 2 * jj) = make_float2(a, b);
    upk2(tk, a, b); *(float2*)(s->bk + mk * 34 + 2 * jj) = make_float2(a, b);
  }
  __syncthreads();

  // ---- edge GEMM: 2 edges x 32 h' per thread; Ws via LDC.128 (no repack) ----
  const int e0 = 2 * tid, m = e0 >> 5, k0 = e0 & 31;
  ull a0[16], a1[16];
#pragma unroll
  for (int j = 0; j < 16; j++) {
    float2 bmv = *(const float2*)(s->bm + m * 34 + 2 * j);
    float2 b0v = *(const float2*)(s->bk + k0 * 34 + 2 * j);
    float2 b1v = *(const float2*)(s->bk + (k0 + 1) * 34 + 2 * j);
    a0[j] = pk2(bmv.x + b0v.x, bmv.y + b0v.y);
    a1[j] = pk2(bmv.x + b1v.x, bmv.y + b1v.y);
  }
#pragma unroll 4
  for (int d = 0; d < DIN; d++) {
    float2 hv = *(const float2*)(src + d * 1024 + e0);
    ull H0 = pk2(hv.x, hv.x), H1 = pk2(hv.y, hv.y);
    const ulonglong2* wrow = (const ulonglong2*)(cws + wofs + d * 32);
#pragma unroll
    for (int q = 0; q < 8; q++) {
      ulonglong2 w = wrow[q];  // LDC.128, pair-typed: used directly, no repack
      fma2(a0[2 * q], H0, w.x);
      fma2(a0[2 * q + 1], H0, w.y);
      fma2(a1[2 * q], H1, w.x);
      fma2(a1[2 * q + 1], H1, w.y);
    }
  }
  // threads touch only their own 2 columns -> in-place is private, no barrier
#pragma unroll
  for (int j = 0; j < 16; j++) {
    float x0, x1, y0, y1;
    upk2(a0[j], x0, x1);
    upk2(a1[j], y0, y1);
    x0 = fmaxf(x0, 0.f); x1 = fmaxf(x1, 0.f);
    y0 = fmaxf(y0, 0.f); y1 = fmaxf(y1, 0.f);
    *(float2*)(s->h + (2 * j) * 1024 + e0) = make_float2(x0, y0);
    *(float2*)(s->h + (2 * j + 1) * 1024 + e0) = make_float2(x1, y1);
  }
  __syncthreads();  // h ready for next layer
}

__global__ void __launch_bounds__(NT, 1) __cluster_dims__(2, 1, 1)
gnn_kernel(Params p) {
  SM* s = (SM*)smem_raw;
  const int tid = threadIdx.x, lane = tid & 31, wid = tid >> 5;
  uint32_t rank;
  asm("mov.u32 %0, %%cluster_ctarank;" : "=r"(rank));
  const uint32_t peer = rank ^ 1u;
  const int sample = blockIdx.x >> 1;

  // stage x -> xs[c][e]
  {
    const float* xg = p.x + (size_t)sample * 4096 + (size_t)rank * 2048;
    float4 v = *(const float4*)(xg + 4 * tid);
    int e0 = 2 * tid;
    s->xs[e0] = v.x; s->xs[e0 + 1] = v.z;
    s->xs[1024 + e0] = v.y; s->xs[1024 + e0 + 1] = v.w;
  }
  __syncthreads();

  // parities: L1:0 L2:1 L3:0 L4:1 L5:0 (overwrite distance 2 => safe)
  layer32<2>(s, s->xs, 0, p.w[1], p.w[2], 0, tid, lane, wid, peer);
  for (int l = 1; l < 4; ++l)
    layer32<32>(s, s->h, l * 1024, p.w[3 * l + 1], p.w[3 * l + 2], l & 1, tid,
                lane, wid, peer);

  // ---- layer 5 (DIN=32, DOUT=2, no relu) + power norm + store ----
  {
    const float* gWs = p.w[12];
    const float* gWm = p.w[13];
    const float* gWk = p.w[14];
    float* mkp = s->mkpL[0];
    if (tid < 64) {  // transposed stride-2 staging
      int d = tid >> 1, hh = tid & 1;
      s->wsT5[d * 2 + hh] = gWs[hh * 32 + d];
      s->wmT[d * 2 + hh] = gWm[hh * 32 + d];
      s->wkT[d * 2 + hh] = gWk[hh * 32 + d];
    }
    msgs<32>(s, s->h, mkp, lane, wid);
    csync();
    combine_mk<32>(s, mkp, tid, peer);
    __syncthreads();
    if (tid < 32) {  // bias: 32 mk x 1 h-pair each
      ull tb = 0, tk = 0;
#pragma unroll
      for (int d = 0; d < 32; d++) {
        ull wmv = *(const ull*)(s->wmT + d * 2);
        ull wkv = *(const ull*)(s->wkT + d * 2);
        float am = s->mm[tid * 34 + d];
        float ak = s->mkc[tid * 34 + d];
        fma2(tb, pk2(am, am), wmv);
        fma2(tk, pk2(ak, ak), wkv);
      }
      float a, b;
      upk2(tb, a, b); *(float2*)(s->bm + tid * 34) = make_float2(a, b);
      upk2(tk, a, b); *(float2*)(s->bk + tid * 34) = make_float2(a, b);
    }
    __syncthreads();

    // 2 edges per thread
    const int e0 = 2 * tid, m = e0 >> 5, k0 = e0 & 31;
    float2 bmv = *(const float2*)(s->bm + m * 34);
    float2 b0v = *(const float2*)(s->bk + k0 * 34);
    float2 b1v = *(const float2*)(s->bk + (k0 + 1) * 34);
    ull a0 = pk2(bmv.x + b0v.x, bmv.y + b0v.y);
    ull a1 = pk2(bmv.x + b1v.x, bmv.y + b1v.y);
#pragma unroll 8
    for (int d = 0; d < 32; d++) {
      float2 hv = *(const float2*)(s->h + d * 1024 + e0);
      ull w = *(const ull*)(s->wsT5 + d * 2);
      fma2(a0, pk2(hv.x, hv.x), w);
      fma2(a1, pk2(hv.y, hv.y), w);
    }
    float x0, x1, y0, y1;
    upk2(a0, x0, x1);
    upk2(a1, y0, y1);

    // power = sum over whole sample of z^2
    float pl = x0 * x0 + x1 * x1 + y0 * y0 + y1 * y1;
    pl += __shfl_xor_sync(0xffffffffu, pl, 1);
    pl += __shfl_xor_sync(0xffffffffu, pl, 2);
    pl += __shfl_xor_sync(0xffffffffu, pl, 4);
    pl += __shfl_xor_sync(0xffffffffu, pl, 8);
    pl += __shfl_xor_sync(0xffffffffu, pl, 16);
    if (lane == 0) s->red[wid] = pl;
    __syncthreads();
    if (tid == 0) {
      float t = 0.f;
#pragma unroll
      for (int w2 = 0; w2 < NW; w2++) t += s->red[w2];
      s->powslot = t;
    }
    csync();  // both CTAs' powslot ready
    float al = rsqrtf(s->powslot + peer_ldf(&s->powslot, peer));  // PT = 1

    float4 o = make_float4(al * x0, al * x1, al * y0, al * y1);
    *(float4*)(p.out + (size_t)sample * 4096 + (size_t)rank * 2048 + 4 * tid) = o;
    csync();  // keep our smem alive until peer finished its powslot read
  }
}

extern "C" void kernel_launch(void* const* d_in, const int* in_sizes, int n_in,
                              void* d_out, int out_size) {
  Params p;
  p.x = (const float*)d_in[0];
  for (int i = 0; i < 15; i++) p.w[i] = (const float*)d_in[1 + i];
  p.out = (float*)d_out;

  // Resolve DEVICE addresses of both symbols (pure queries; cached).
  static void* cws_dev = nullptr;
  static void* wstage_dev = nullptr;
  if (cws_dev == nullptr) {
    cudaGetSymbolAddress(&cws_dev, cws);
    cudaGetSymbolAddress(&wstage_dev, wstage);
  }

  // 1) transpose Ws(1-4) into wstage   2) D2D copy into the constant bank
  prep_kernel<<<1, NT>>>((const float*)d_in[1], (const float*)d_in[4],
                         (const float*)d_in[7], (const float*)d_in[10]);
  cudaMemcpyAsync(cws_dev, wstage_dev, 4096 * sizeof(float),
                  cudaMemcpyDeviceToDevice);

  cudaFuncSetAttribute(gnn_kernel, cudaFuncAttributeMaxDynamicSharedMemorySize,
                       (int)sizeof(SM));
  gnn_kernel<<<2048, NT, sizeof(SM)>>>(p);
}

// round 11
// speedup vs baseline: 1.0517x; 1.0517x over previous
#include <cuda_runtime.h>
#include <cstdint>

// Fully fused Precoding-GNN, R11: one sample per 4-CTA cluster, 16 antennas
// (512 edges) per CTA -> ~104KB smem/CTA -> TWO co-resident CTAs per SM.
// Independent CTAs fill each other's phase/barrier bubbles (R5/R10 showed the
// single-CTA design is serialization-bound, not pipe-bound).
// Per-thread structure identical to the proven R3: NT=256, 2 edges x 32 h'
// f32x2 edge GEMM with LDS.128 weight broadcasts, zero-repack register shape.
// BS=1024, M=64, K=32, D=32. h layout: h[d][e], e = m_loc*32+k (pitch 512).

#define NT 256
#define NW 8
#define EPC 512   // edges per CTA
#define MLOC 16   // antennas per CTA

typedef unsigned long long ull;

struct SM {
  float h[32 * EPC];       // 65536 B hidden state [d][e]
  float xs[2 * EPC];       //  4096 B layer-1 input [c][e]
  float wsT[1024];         //  4096 B Ws^T: wsT[d*32+h] (stride 2 for L5)
  float wmT[1024];         //  4096 B Wm^T: wmT[d*32+h]
  float wkT[1024];         //  4096 B Wk^T
  float mm[MLOC * 34];     //  2176 B msg_m[m][d] (pitch 34)
  float mkpL[2][32 * 34];  //  8704 B msg_k partial [k][d], parity buffered
  float mkc[32 * 34];      //  4352 B msg_k combined [k][d]
  float bm[MLOC * 34];     //  2176 B Wm@msg_m [m][h]
  float bk[32 * 34];       //  4352 B Wk@msg_k [k][h]
  float red[NW];
  float powslot;
};

struct Params {
  const float* x;
  const float* w[15];
  float* out;
};

extern __shared__ __align__(16) char smem_raw[];

__device__ __forceinline__ uint32_t s2u(const void* p) {
  uint32_t a;
  asm("{ .reg .u64 t; cvta.to.shared.u64 t, %1; cvt.u32.u64 %0, t; }"
      : "=r"(a) : "l"(p));
  return a;
}
__device__ __forceinline__ float peer_ldf(const float* p, uint32_t peer) {
  uint32_t ra;
  asm("mapa.shared::cluster.u32 %0, %1, %2;" : "=r"(ra) : "r"(s2u(p)), "r"(peer));
  float v;
  asm volatile("ld.shared::cluster.f32 %0, [%1];" : "=f"(v) : "r"(ra));
  return v;
}
__device__ __forceinline__ float2 peer_ldf2(const float* p, uint32_t peer) {
  uint32_t ra;
  asm("mapa.shared::cluster.u32 %0, %1, %2;" : "=r"(ra) : "r"(s2u(p)), "r"(peer));
  float2 v;
  asm volatile("ld.shared::cluster.v2.f32 {%0,%1}, [%2];"
               : "=f"(v.x), "=f"(v.y) : "r"(ra));
  return v;
}
__device__ __forceinline__ void csync() {
  asm volatile("barrier.cluster.arrive.aligned;" ::: "memory");
  asm volatile("barrier.cluster.wait.aligned;" ::: "memory");
}
__device__ __forceinline__ ull pk2(float x, float y) {
  ull r; asm("mov.b64 %0,{%1,%2};" : "=l"(r) : "f"(x), "f"(y)); return r;
}
__device__ __forceinline__ void upk2(ull v, float& x, float& y) {
  asm("mov.b64 {%0,%1},%2;" : "=f"(x), "=f"(y) : "l"(v));
}
__device__ __forceinline__ void fma2(ull& d, ull a, ull b) {
  asm("fma.rn.f32x2 %0,%1,%2,%0;" : "+l"(d) : "l"(a), "l"(b));
}

// msg_m[m][d] = sum_k src[d][m*32+k]  (m local, contiguous float4 + shfl tree)
// mkp[k][d]  = sum over 16 local antennas of src[d][m*32+k]
template <int DIN>
__device__ __forceinline__ void msgs(SM* s, const float* src, float* mkp,
                                     int lane, int wid) {
  for (int r = wid; r < DIN * 4; r += NW) {
    int d = r >> 2, g = r & 3;  // g: group of 4 antennas (128 floats)
    float4 v = *(const float4*)(src + d * EPC + g * 128 + lane * 4);
    float t = v.x + v.y + v.z + v.w;
    t += __shfl_xor_sync(0xffffffffu, t, 1);
    t += __shfl_xor_sync(0xffffffffu, t, 2);
    t += __shfl_xor_sync(0xffffffffu, t, 4);
    if ((lane & 7) == 0) s->mm[(g * 4 + (lane >> 3)) * 34 + d] = t;
  }
  for (int d = wid; d < DIN; d += NW) {
    float t = 0.f;
#pragma unroll
    for (int m2 = 0; m2 < MLOC; m2++) t += src[d * EPC + m2 * 32 + lane];
    mkp[lane * 34 + d] = t;
  }
}

// combine: mkc = mkp(local) + 3 cluster peers, float2 granularity
template <int DIN>
__device__ __forceinline__ void combine_mk(SM* s, const float* mkp, int tid,
                                           uint32_t rank) {
  constexpr int PAIRS = 32 * DIN / 2;
  const uint32_t p1 = (rank + 1) & 3, p2 = (rank + 2) & 3, p3 = (rank + 3) & 3;
  for (int i = tid; i < PAIRS; i += NT) {
    int k = i / (DIN / 2), dp = i % (DIN / 2);
    int off = k * 34 + 2 * dp;
    float2 a = *(const float2*)(mkp + off);
    float2 b = peer_ldf2(mkp + off, p1);
    float2 c = peer_ldf2(mkp + off, p2);
    float2 e = peer_ldf2(mkp + off, p3);
    *(float2*)(s->mkc + off) =
        make_float2(a.x + b.x + c.x + e.x, a.y + b.y + c.y + e.y);
  }
}

// One GNN layer, DOUT=32, relu. src = xs (L1) or h (L2-4), dest = h in place.
template <int DIN>
__device__ __forceinline__ void layer32(SM* s, const float* src,
                                        const float* gWs, const float* gWm,
                                        const float* gWk, int par, int tid,
                                        int lane, int wid, uint32_t rank) {
  float* mkp = s->mkpL[par];
  // stage transposed weights: wT[d*32 + h]
  for (int i = tid; i < DIN * 32; i += NT) {
    int d = i >> 5, hh = i & 31;
    s->wsT[i] = gWs[hh * DIN + d];
    s->wmT[i] = gWm[hh * DIN + d];
    s->wkT[i] = gWk[hh * DIN + d];
  }
  msgs<DIN>(s, src, mkp, lane, wid);
  csync();  // mkp visible cluster-wide; also orders local staging/mm
  combine_mk<DIN>(s, mkp, tid, rank);
  __syncthreads();
  // bias GEMMs (f32x2). bk: 512 slots (2/thread); bm: 256 slots (1/thread).
  {
    const int jj = tid & 15;
#pragma unroll
    for (int half = 0; half < 2; half++) {
      const int mk = (tid >> 4) + half * 16;
      ull tk = 0;
#pragma unroll
      for (int d = 0; d < DIN; d++) {
        ull wkv = *(const ull*)(s->wkT + d * 32 + 2 * jj);
        float ak = s->mkc[mk * 34 + d];
        fma2(tk, pk2(ak, ak), wkv);
      }
      float a, b;
      upk2(tk, a, b);
      *(float2*)(s->bk + mk * 34 + 2 * jj) = make_float2(a, b);
    }
    const int m = tid >> 4;  // 0..15
    ull tb = 0;
#pragma unroll
    for (int d = 0; d < DIN; d++) {
      ull wmv = *(const ull*)(s->wmT + d * 32 + 2 * jj);
      float am = s->mm[m * 34 + d];
      fma2(tb, pk2(am, am), wmv);
    }
    float a, b;
    upk2(tb, a, b);
    *(float2*)(s->bm + m * 34 + 2 * jj) = make_float2(a, b);
  }
  __syncthreads();

  // ---- edge GEMM: 2 edges x 32 h' per thread (R3-exact shape) ----
  const int e0 = 2 * tid, m = e0 >> 5, k0 = e0 & 31;
  ull a0[16], a1[16];
#pragma unroll
  for (int j = 0; j < 16; j++) {
    float2 bmv = *(const float2*)(s->bm + m * 34 + 2 * j);
    float2 b0v = *(const float2*)(s->bk + k0 * 34 + 2 * j);
    float2 b1v = *(const float2*)(s->bk + (k0 + 1) * 34 + 2 * j);
    a0[j] = pk2(bmv.x + b0v.x, bmv.y + b0v.y);
    a1[j] = pk2(bmv.x + b1v.x, bmv.y + b1v.y);
  }
#pragma unroll 4
  for (int d = 0; d < DIN; d++) {
    float2 hv = *(const float2*)(src + d * EPC + e0);
    ull H0 = pk2(hv.x, hv.x), H1 = pk2(hv.y, hv.y);
    const ulonglong2* wr = (const ulonglong2*)(s->wsT + d * 32);
#pragma unroll
    for (int q = 0; q < 8; q++) {
      ulonglong2 w = wr[q];  // broadcast LDS.128, used directly (no repack)
      fma2(a0[2 * q], H0, w.x);
      fma2(a0[2 * q + 1], H0, w.y);
      fma2(a1[2 * q], H1, w.x);
      fma2(a1[2 * q + 1], H1, w.y);
    }
  }
  // threads touch only their own 2 columns -> in-place is private, no barrier
#pragma unroll
  for (int j = 0; j < 16; j++) {
    float x0, x1, y0, y1;
    upk2(a0[j], x0, x1);
    upk2(a1[j], y0, y1);
    x0 = fmaxf(x0, 0.f); x1 = fmaxf(x1, 0.f);
    y0 = fmaxf(y0, 0.f); y1 = fmaxf(y1, 0.f);
    *(float2*)(s->h + (2 * j) * EPC + e0) = make_float2(x0, y0);
    *(float2*)(s->h + (2 * j + 1) * EPC + e0) = make_float2(x1, y1);
  }
  __syncthreads();  // h ready for next layer
}

__global__ void __launch_bounds__(NT, 2) __cluster_dims__(4, 1, 1)
gnn_kernel(Params p) {
  SM* s = (SM*)smem_raw;
  const int tid = threadIdx.x, lane = tid & 31, wid = tid >> 5;
  uint32_t rank;
  asm("mov.u32 %0, %%cluster_ctarank;" : "=r"(rank));
  const int sample = blockIdx.x >> 2;

  // stage x -> xs[c][e]: CTA owns antennas [16*rank, 16*rank+16)
  {
    const float* xg = p.x + (size_t)sample * 4096 + (size_t)rank * 1024;
    float4 v = *(const float4*)(xg + 4 * tid);
    int e0 = 2 * tid;
    s->xs[e0] = v.x; s->xs[e0 + 1] = v.z;
    s->xs[EPC + e0] = v.y; s->xs[EPC + e0 + 1] = v.w;
  }
  __syncthreads();

  // parities: L1:0 L2:1 L3:0 L4:1 L5:0 (overwrite distance 2 => safe)
  layer32<2>(s, s->xs, p.w[0], p.w[1], p.w[2], 0, tid, lane, wid, rank);
  for (int l = 1; l < 4; ++l)
    layer32<32>(s, s->h, p.w[3 * l], p.w[3 * l + 1], p.w[3 * l + 2], l & 1,
                tid, lane, wid, rank);

  // ---- layer 5 (DIN=32, DOUT=2, no relu) + power norm + store ----
  {
    const float* gWs = p.w[12];
    const float* gWm = p.w[13];
    const float* gWk = p.w[14];
    float* mkp = s->mkpL[0];
    if (tid < 64) {  // transposed stride-2 staging into wsT/wmT/wkT
      int d = tid >> 1, hh = tid & 1;
      s->wsT[d * 2 + hh] = gWs[hh * 32 + d];
      s->wmT[d * 2 + hh] = gWm[hh * 32 + d];
      s->wkT[d * 2 + hh] = gWk[hh * 32 + d];
    }
    msgs<32>(s, s->h, mkp, lane, wid);
    csync();
    combine_mk<32>(s, mkp, tid, rank);
    __syncthreads();
    if (tid < 32) {  // bias: bk for 32 k's; bm for 16 m's
      ull tk = 0;
#pragma unroll
      for (int d = 0; d < 32; d++) {
        ull wkv = *(const ull*)(s->wkT + d * 2);
        float ak = s->mkc[tid * 34 + d];
        fma2(tk, pk2(ak, ak), wkv);
      }
      float a, b;
      upk2(tk, a, b);
      *(float2*)(s->bk + tid * 34) = make_float2(a, b);
      if (tid < MLOC) {
        ull tb = 0;
#pragma unroll
        for (int d = 0; d < 32; d++) {
          ull wmv = *(const ull*)(s->wmT + d * 2);
          float am = s->mm[tid * 34 + d];
          fma2(tb, pk2(am, am), wmv);
        }
        upk2(tb, a, b);
        *(float2*)(s->bm + tid * 34) = make_float2(a, b);
      }
    }
    __syncthreads();

    // 2 edges per thread
    const int e0 = 2 * tid, m = e0 >> 5, k0 = e0 & 31;
    float2 bmv = *(const float2*)(s->bm + m * 34);
    float2 b0v = *(const float2*)(s->bk + k0 * 34);
    float2 b1v = *(const float2*)(s->bk + (k0 + 1) * 34);
    ull a0 = pk2(bmv.x + b0v.x, bmv.y + b0v.y);
    ull a1 = pk2(bmv.x + b1v.x, bmv.y + b1v.y);
#pragma unroll 8
    for (int d = 0; d < 32; d++) {
      float2 hv = *(const float2*)(s->h + d * EPC + e0);
      ull w = *(const ull*)(s->wsT + d * 2);
      fma2(a0, pk2(hv.x, hv.x), w);
      fma2(a1, pk2(hv.y, hv.y), w);
    }
    float x0, x1, y0, y1;
    upk2(a0, x0, x1);
    upk2(a1, y0, y1);

    // power = sum over whole sample of z^2 (CTA partial, then 4 slots)
    float pl = x0 * x0 + x1 * x1 + y0 * y0 + y1 * y1;
    pl += __shfl_xor_sync(0xffffffffu, pl, 1);
    pl += __shfl_xor_sync(0xffffffffu, pl, 2);
    pl += __shfl_xor_sync(0xffffffffu, pl, 4);
    pl += __shfl_xor_sync(0xffffffffu, pl, 8);
    pl += __shfl_xor_sync(0xffffffffu, pl, 16);
    if (lane == 0) s->red[wid] = pl;
    __syncthreads();
    if (tid == 0) {
      float t = 0.f;
#pragma unroll
      for (int w2 = 0; w2 < NW; w2++) t += s->red[w2];
      s->powslot = t;
    }
    csync();  // all 4 CTAs' powslot ready
    float pw = s->powslot;
#pragma unroll
    for (int r2 = 1; r2 < 4; r2++)
      pw += peer_ldf(&s->powslot, (rank + r2) & 3);
    float al = rsqrtf(pw);  // PT = 1

    float4 o = make_float4(al * x0, al * x1, al * y0, al * y1);
    *(float4*)(p.out + (size_t)sample * 4096 + (size_t)rank * 1024 + 4 * tid) = o;
    csync();  // keep our smem alive until peers finished powslot reads
  }
}

extern "C" void kernel_launch(void* const* d_in, const int* in_sizes, int n_in,
                              void* d_out, int out_size) {
  Params p;
  p.x = (const float*)d_in[0];
  for (int i = 0; i < 15; i++) p.w[i] = (const float*)d_in[1 + i];
  p.out = (float*)d_out;
  cudaFuncSetAttribute(gnn_kernel, cudaFuncAttributeMaxDynamicSharedMemorySize,
                       (int)sizeof(SM));
  gnn_kernel<<<4096, NT, sizeof(SM)>>>(p);
}

// round 12
// speedup vs baseline: 1.1805x; 1.1225x over previous
#include <cuda_runtime.h>
#include <cstdint>

// Fully fused Precoding-GNN, R12: R3 base (proven 581us) with the edge GEMM
// retiled to E=8 edges x H=8 outputs per thread -> 4 LSU instructions per
// 64 FMA-cycles per d (vs R3's 9). Register-lean (acc=64 regs, zero repacks).
// One sample per 2-CTA cluster, hidden state resident in SMEM all 5 layers.
// BS=1024, M=64, K=32, D=32. Each CTA owns 32 antennas -> 1024 edges.
// h layout: h[d][e], e = m_loc*32 + k (pitch 1024 floats).

#define NT 512
#define NW 16

typedef unsigned long long ull;

struct SM {
  float h[32 * 1024];      // 131072 B hidden state [d][e]
  float xs[2 * 1024];      //   8192 B layer-1 input [c][e]
  float wsT[1024];         //   4096 B Ws^T: wsT[d*32+h] (stride 2 for L5)
  float wm[1024];          //   4096 B Wm row-major (as in gmem)
  float wk[1024];          //   4096 B Wk row-major
  float mm[32 * 34];       //   4352 B msg_m[m][d]      (pitch 34)
  float mkpL[2][32 * 34];  //   8704 B msg_k partial [k][d], parity buffered
  float mkc[32 * 34];      //   4352 B msg_k combined [k][d]
  float bm[32 * 34];       //   4352 B Wm@msg_m  [m][h]
  float bk[32 * 34];       //   4352 B Wk@msg_k  [k][h]
  float red[NW];
  float powslot;
};

struct Params {
  const float* x;
  const float* w[15];
  float* out;
};

extern __shared__ __align__(16) char smem_raw[];

__device__ __forceinline__ uint32_t s2u(const void* p) {
  uint32_t a;
  asm("{ .reg .u64 t; cvta.to.shared.u64 t, %1; cvt.u32.u64 %0, t; }"
      : "=r"(a) : "l"(p));
  return a;
}
__device__ __forceinline__ float peer_ldf(const float* p, uint32_t peer) {
  uint32_t ra;
  asm("mapa.shared::cluster.u32 %0, %1, %2;" : "=r"(ra) : "r"(s2u(p)), "r"(peer));
  float v;
  asm volatile("ld.shared::cluster.f32 %0, [%1];" : "=f"(v) : "r"(ra));
  return v;
}
__device__ __forceinline__ float2 peer_ldf2(const float* p, uint32_t peer) {
  uint32_t ra;
  asm("mapa.shared::cluster.u32 %0, %1, %2;" : "=r"(ra) : "r"(s2u(p)), "r"(peer));
  float2 v;
  asm volatile("ld.shared::cluster.v2.f32 {%0,%1}, [%2];"
               : "=f"(v.x), "=f"(v.y) : "r"(ra));
  return v;
}
__device__ __forceinline__ void csync() {
  asm volatile("barrier.cluster.arrive.aligned;" ::: "memory");
  asm volatile("barrier.cluster.wait.aligned;" ::: "memory");
}
__device__ __forceinline__ ull pk2(float x, float y) {
  ull r; asm("mov.b64 %0,{%1,%2};" : "=l"(r) : "f"(x), "f"(y)); return r;
}
__device__ __forceinline__ void upk2(ull v, float& x, float& y) {
  asm("mov.b64 {%0,%1},%2;" : "=f"(x), "=f"(y) : "l"(v));
}
__device__ __forceinline__ void fma2(ull& d, ull a, ull b) {
  asm("fma.rn.f32x2 %0,%1,%2,%0;" : "+l"(d) : "l"(a), "l"(b));
}

// msg_m[m][d] = sum_k src[d][m*32+k]  (contiguous float4 loads, shfl tree)
// mkp[k][d]  = sum_{m_loc} src[d][m*32+k]  (contiguous-lane, serial over m)
template <int DIN>
__device__ __forceinline__ void msgs(SM* s, const float* src, float* mkp,
                                     int lane, int wid) {
  for (int r = wid; r < DIN * 8; r += NW) {
    int d = r >> 3, g = r & 7;  // g: group of 4 antennas (128 floats)
    float4 v = *(const float4*)(src + d * 1024 + g * 128 + lane * 4);
    float t = v.x + v.y + v.z + v.w;
    t += __shfl_xor_sync(0xffffffffu, t, 1);
    t += __shfl_xor_sync(0xffffffffu, t, 2);
    t += __shfl_xor_sync(0xffffffffu, t, 4);
    if ((lane & 7) == 0) s->mm[(g * 4 + (lane >> 3)) * 34 + d] = t;
  }
  for (int d = wid; d < DIN; d += NW) {
    float t = 0.f;
#pragma unroll
    for (int m2 = 0; m2 < 32; m2++) t += src[d * 1024 + m2 * 32 + lane];
    mkp[lane * 34 + d] = t;
  }
}

// combine: mkc = mkp(local) + mkp(peer), float2 granularity
template <int DIN>
__device__ __forceinline__ void combine_mk(SM* s, const float* mkp, int tid,
                                           uint32_t peer) {
  constexpr int PAIRS = 32 * DIN / 2;
  for (int i = tid; i < PAIRS; i += NT) {
    int k = i / (DIN / 2), dp = i % (DIN / 2);
    int off = k * 34 + 2 * dp;
    float2 a = *(const float2*)(mkp + off);
    float2 b = peer_ldf2(mkp + off, peer);
    *(float2*)(s->mkc + off) = make_float2(a.x + b.x, a.y + b.y);
  }
}

// One GNN layer, DOUT=32, relu. src = xs (L1) or h (L2-4), dest = h in place.
template <int DIN>
__device__ __forceinline__ void layer32(SM* s, const float* src,
                                        const float* gWs, const float* gWm,
                                        const float* gWk, int par, int tid,
                                        int lane, int wid, uint32_t peer) {
  float* mkp = s->mkpL[par];
  // stage weights (Ws transposed; Wm/Wk row-major as in gmem)
  for (int i = tid; i < DIN * 32; i += NT) {
    int d = i >> 5, hh = i & 31;
    s->wsT[d * 32 + hh] = gWs[hh * DIN + d];
  }
  for (int i = tid; i < 32 * DIN; i += NT) {
    s->wm[i] = gWm[i];
    s->wk[i] = gWk[i];
  }
  msgs<DIN>(s, src, mkp, lane, wid);
  csync();  // mkp visible cluster-wide; also orders local staging/mm
  combine_mk<DIN>(s, mkp, tid, peer);
  __syncthreads();
  // bias GEMMs: bm[m][h] = Wm@msg_m, bk[k][h] = Wk@msg_k (R3-exact)
  for (int p = tid; p < 1024; p += NT) {
    int hh = p >> 5, mk = p & 31;  // hh warp-uniform -> wm/wk broadcast
    float tb = 0.f, tk = 0.f;
#pragma unroll
    for (int d = 0; d < DIN; d++) {
      tb += s->wm[hh * DIN + d] * s->mm[mk * 34 + d];
      tk += s->wk[hh * DIN + d] * s->mkc[mk * 34 + d];
    }
    s->bm[mk * 34 + hh] = tb;
    s->bk[mk * 34 + hh] = tk;
  }
  __syncthreads();

  // ---- edge GEMM: 8 edges x 8 h' per thread ----
  // cg: edge octet (128 per CTA); hg: h'-slice (4 slices of 8)
  const int cg = tid & 127, hg = tid >> 7;
  const int hb = hg * 8;
  const int e0 = 8 * cg;                 // all 8 edges share antenna m
  const int m = e0 >> 5, k0 = e0 & 31;

  ull acc[8][4];
#pragma unroll
  for (int j = 0; j < 4; j++) {
    float2 bmv = *(const float2*)(s->bm + m * 34 + hb + 2 * j);
#pragma unroll
    for (int e = 0; e < 8; e++) {
      float2 bkv = *(const float2*)(s->bk + (k0 + e) * 34 + hb + 2 * j);
      acc[e][j] = pk2(bmv.x + bkv.x, bmv.y + bkv.y);
    }
  }
#pragma unroll 4
  for (int d = 0; d < DIN; d++) {
    const float* hp = src + d * 1024 + e0;
    float4 ha = *(const float4*)hp;
    float4 hc = *(const float4*)(hp + 4);
    const ulonglong2* wr = (const ulonglong2*)(s->wsT + d * 32 + hb);
    ulonglong2 w0 = wr[0], w1 = wr[1];  // broadcast LDS.128 x2, no repack
    ull H;
    H = pk2(ha.x, ha.x);
    fma2(acc[0][0], H, w0.x); fma2(acc[0][1], H, w0.y);
    fma2(acc[0][2], H, w1.x); fma2(acc[0][3], H, w1.y);
    H = pk2(ha.y, ha.y);
    fma2(acc[1][0], H, w0.x); fma2(acc[1][1], H, w0.y);
    fma2(acc[1][2], H, w1.x); fma2(acc[1][3], H, w1.y);
    H = pk2(ha.z, ha.z);
    fma2(acc[2][0], H, w0.x); fma2(acc[2][1], H, w0.y);
    fma2(acc[2][2], H, w1.x); fma2(acc[2][3], H, w1.y);
    H = pk2(ha.w, ha.w);
    fma2(acc[3][0], H, w0.x); fma2(acc[3][1], H, w0.y);
    fma2(acc[3][2], H, w1.x); fma2(acc[3][3], H, w1.y);
    H = pk2(hc.x, hc.x);
    fma2(acc[4][0], H, w0.x); fma2(acc[4][1], H, w0.y);
    fma2(acc[4][2], H, w1.x); fma2(acc[4][3], H, w1.y);
    H = pk2(hc.y, hc.y);
    fma2(acc[5][0], H, w0.x); fma2(acc[5][1], H, w0.y);
    fma2(acc[5][2], H, w1.x); fma2(acc[5][3], H, w1.y);
    H = pk2(hc.z, hc.z);
    fma2(acc[6][0], H, w0.x); fma2(acc[6][1], H, w0.y);
    fma2(acc[6][2], H, w1.x); fma2(acc[6][3], H, w1.y);
    H = pk2(hc.w, hc.w);
    fma2(acc[7][0], H, w0.x); fma2(acc[7][1], H, w0.y);
    fma2(acc[7][2], H, w1.x); fma2(acc[7][3], H, w1.y);
  }
  __syncthreads();  // other h'-slices read our columns: finish reads first

  // epilogue: relu + 16x STS.128 (in place into h)
#pragma unroll
  for (int j = 0; j < 4; j++) {
    float lo[8], hi[8];
#pragma unroll
    for (int e = 0; e < 8; e++) {
      upk2(acc[e][j], lo[e], hi[e]);
      lo[e] = fmaxf(lo[e], 0.f);
      hi[e] = fmaxf(hi[e], 0.f);
    }
    float* r0 = s->h + (hb + 2 * j) * 1024 + e0;
    float* r1 = s->h + (hb + 2 * j + 1) * 1024 + e0;
    *(float4*)r0 = make_float4(lo[0], lo[1], lo[2], lo[3]);
    *(float4*)(r0 + 4) = make_float4(lo[4], lo[5], lo[6], lo[7]);
    *(float4*)r1 = make_float4(hi[0], hi[1], hi[2], hi[3]);
    *(float4*)(r1 + 4) = make_float4(hi[4], hi[5], hi[6], hi[7]);
  }
  __syncthreads();  // h ready for next layer
}

__global__ void __launch_bounds__(NT, 1) __cluster_dims__(2, 1, 1)
gnn_kernel(Params p) {
  SM* s = (SM*)smem_raw;
  const int tid = threadIdx.x, lane = tid & 31, wid = tid >> 5;
  uint32_t rank;
  asm("mov.u32 %0, %%cluster_ctarank;" : "=r"(rank));
  const uint32_t peer = rank ^ 1u;
  const int sample = blockIdx.x >> 1;

  // stage x -> xs[c][e]
  {
    const float* xg = p.x + (size_t)sample * 4096 + (size_t)rank * 2048;
    float4 v = *(const float4*)(xg + 4 * tid);
    int e0 = 2 * tid;
    s->xs[e0] = v.x; s->xs[e0 + 1] = v.z;
    s->xs[1024 + e0] = v.y; s->xs[1024 + e0 + 1] = v.w;
  }
  __syncthreads();

  // parities: L1:0 L2:1 L3:0 L4:1 L5:0 (overwrite distance 2 => safe)
  layer32<2>(s, s->xs, p.w[0], p.w[1], p.w[2], 0, tid, lane, wid, peer);
  for (int l = 1; l < 4; ++l)
    layer32<32>(s, s->h, p.w[3 * l], p.w[3 * l + 1], p.w[3 * l + 2], l & 1,
                tid, lane, wid, peer);

  // ---- layer 5 (DIN=32, DOUT=2, no relu) + power norm + store ----
  {
    const float* gWs = p.w[12];
    const float* gWm = p.w[13];
    const float* gWk = p.w[14];
    float* mkp = s->mkpL[0];
    if (tid < 64) {  // Ws^T stride-2; Wm/Wk row-major (2,32) straight copy
      int d = tid >> 1, hh = tid & 1;
      s->wsT[d * 2 + hh] = gWs[hh * 32 + d];
      s->wm[tid] = gWm[tid];
      s->wk[tid] = gWk[tid];
    }
    msgs<32>(s, s->h, mkp, lane, wid);
    csync();
    combine_mk<32>(s, mkp, tid, peer);
    __syncthreads();
    if (tid < 64) {  // bias: 32 mk x 2 h' slots (scalar, R3-exact)
      int hh = tid >> 5, mk = tid & 31;
      float tb = 0.f, tk = 0.f;
#pragma unroll
      for (int d = 0; d < 32; d++) {
        tb += s->wm[hh * 32 + d] * s->mm[mk * 34 + d];
        tk += s->wk[hh * 32 + d] * s->mkc[mk * 34 + d];
      }
      s->bm[mk * 34 + hh] = tb;
      s->bk[mk * 34 + hh] = tk;
    }
    __syncthreads();

    // 2 edges per thread
    const int e0 = 2 * tid, m = e0 >> 5, k0 = e0 & 31;
    float2 bmv = *(const float2*)(s->bm + m * 34);
    float2 b0v = *(const float2*)(s->bk + k0 * 34);
    float2 b1v = *(const float2*)(s->bk + (k0 + 1) * 34);
    ull a0 = pk2(bmv.x + b0v.x, bmv.y + b0v.y);
    ull a1 = pk2(bmv.x + b1v.x, bmv.y + b1v.y);
#pragma unroll 8
    for (int d = 0; d < 32; d++) {
      float2 hv = *(const float2*)(s->h + d * 1024 + e0);
      ull w = *(const ull*)(s->wsT + d * 2);
      fma2(a0, pk2(hv.x, hv.x), w);
      fma2(a1, pk2(hv.y, hv.y), w);
    }
    float x0, x1, y0, y1;
    upk2(a0, x0, x1);
    upk2(a1, y0, y1);

    // power = sum over whole sample of z^2
    float pl = x0 * x0 + x1 * x1 + y0 * y0 + y1 * y1;
    pl += __shfl_xor_sync(0xffffffffu, pl, 1);
    pl += __shfl_xor_sync(0xffffffffu, pl, 2);
    pl += __shfl_xor_sync(0xffffffffu, pl, 4);
    pl += __shfl_xor_sync(0xffffffffu, pl, 8);
    pl += __shfl_xor_sync(0xffffffffu, pl, 16);
    if (lane == 0) s->red[wid] = pl;
    __syncthreads();
    if (tid == 0) {
      float t = 0.f;
#pragma unroll
      for (int w2 = 0; w2 < NW; w2++) t += s->red[w2];
      s->powslot = t;
    }
    csync();  // both CTAs' powslot ready
    float al = rsqrtf(s->powslot + peer_ldf(&s->powslot, peer));  // PT = 1

    float4 o = make_float4(al * x0, al * x1, al * y0, al * y1);
    *(float4*)(p.out + (size_t)sample * 4096 + (size_t)rank * 2048 + 4 * tid) = o;
    csync();  // keep our smem alive until peer finished its powslot read
  }
}

extern "C" void kernel_launch(void* const* d_in, const int* in_sizes, int n_in,
                              void* d_out, int out_size) {
  Params p;
  p.x = (const float*)d_in[0];
  for (int i = 0; i < 15; i++) p.w[i] = (const float*)d_in[1 + i];
  p.out = (float*)d_out;
  cudaFuncSetAttribute(gnn_kernel, cudaFuncAttributeMaxDynamicSharedMemorySize,
                       (int)sizeof(SM));
  gnn_kernel<<<2048, NT, sizeof(SM)>>>(p);
}

// round 13
// speedup vs baseline: 1.2830x; 1.0868x over previous
#include <cuda_runtime.h>
#include <cstdint>

// Fully fused Precoding-GNN, R13: R3 base with MIO-waste removal:
//  - msg tables transposed to [d][*] pitch 33 (conflict-free, coalesced)
//  - bias GEMM computes both h'-slots per thread in one pass (shared mk reads)
//  - wm/wk staged row-major with float4 copies (no transpose scatter)
// Edge GEMM / barriers / registers byte-identical to the proven R3 (581us).
// One sample per 2-CTA cluster, hidden state resident in SMEM all 5 layers.
// BS=1024, M=64, K=32, D=32. Each CTA owns 32 antennas -> 1024 edges.
// h layout: h[d][e], e = m_loc*32 + k (pitch 1024 floats).

#define NT 512
#define NW 16
#define TP 33  // transposed-table pitch: bank = (d + mk) % 32, conflict-free

typedef unsigned long long ull;

struct SM {
  float h[32 * 1024];      // 131072 B hidden state [d][e]
  float xs[2 * 1024];      //   8192 B layer-1 input [c][e]
  float wsT[1024];         //   4096 B Ws^T: wsT[d*32+h] (stride 2 for L5)
  float wm[1024];          //   4096 B Wm row-major (as in gmem)
  float wk[1024];          //   4096 B Wk row-major
  float mmT[32 * TP];      //   4224 B msg_m^T [d][m]
  float mkpT[2][32 * TP];  //   8448 B msg_k partial^T [d][k], parity buffered
  float mkcT[32 * TP];     //   4224 B msg_k combined^T [d][k]
  float bm[32 * 34];       //   4352 B Wm@msg_m  [m][h]  (row layout, pitch 34)
  float bk[32 * 34];       //   4352 B Wk@msg_k  [k][h]
  float red[NW];
  float powslot;
};

struct Params {
  const float* x;
  const float* w[15];
  float* out;
};

extern __shared__ __align__(16) char smem_raw[];

__device__ __forceinline__ uint32_t s2u(const void* p) {
  uint32_t a;
  asm("{ .reg .u64 t; cvta.to.shared.u64 t, %1; cvt.u32.u64 %0, t; }"
      : "=r"(a) : "l"(p));
  return a;
}
__device__ __forceinline__ float peer_ldf(const float* p, uint32_t peer) {
  uint32_t ra;
  asm("mapa.shared::cluster.u32 %0, %1, %2;" : "=r"(ra) : "r"(s2u(p)), "r"(peer));
  float v;
  asm volatile("ld.shared::cluster.f32 %0, [%1];" : "=f"(v) : "r"(ra));
  return v;
}
__device__ __forceinline__ void csync() {
  asm volatile("barrier.cluster.arrive.aligned;" ::: "memory");
  asm volatile("barrier.cluster.wait.aligned;" ::: "memory");
}
__device__ __forceinline__ ull pk2(float x, float y) {
  ull r; asm("mov.b64 %0,{%1,%2};" : "=l"(r) : "f"(x), "f"(y)); return r;
}
__device__ __forceinline__ void upk2(ull v, float& x, float& y) {
  asm("mov.b64 {%0,%1},%2;" : "=f"(x), "=f"(y) : "l"(v));
}
__device__ __forceinline__ void fma2(ull& d, ull a, ull b) {
  asm("fma.rn.f32x2 %0,%1,%2,%0;" : "+l"(d) : "l"(a), "l"(b));
}

// mmT[d][m] = sum_k src[d][m*32+k]  (contiguous float4 loads, 8-lane tree)
// mkpT[d][k] = sum_{m_loc} src[d][m*32+k]  (coalesced lanes, serial over m)
template <int DIN>
__device__ __forceinline__ void msgs(SM* s, const float* src, float* mkpT,
                                     int lane, int wid) {
  for (int r = wid; r < DIN * 8; r += NW) {
    int d = r >> 3, g = r & 7;  // g: group of 4 antennas (128 floats)
    float4 v = *(const float4*)(src + d * 1024 + g * 128 + lane * 4);
    float t = v.x + v.y + v.z + v.w;
    t += __shfl_xor_sync(0xffffffffu, t, 1);
    t += __shfl_xor_sync(0xffffffffu, t, 2);
    t += __shfl_xor_sync(0xffffffffu, t, 4);
    if ((lane & 7) == 0) s->mmT[d * TP + (g * 4 + (lane >> 3))] = t;
  }
  for (int d = wid; d < DIN; d += NW) {
    float t = 0.f;
#pragma unroll
    for (int m2 = 0; m2 < 32; m2++) t += src[d * 1024 + m2 * 32 + lane];
    mkpT[d * TP + lane] = t;  // coalesced, conflict-free
  }
}

// combine: mkcT = mkpT(local) + mkpT(peer); fully coalesced scalar
template <int DIN>
__device__ __forceinline__ void combine_mk(SM* s, const float* mkpT, int tid,
                                           uint32_t peer) {
  for (int i = tid; i < 32 * DIN; i += NT) {
    int d = i >> 5, k = i & 31;  // k = lane -> coalesced
    int off = d * TP + k;
    s->mkcT[off] = mkpT[off] + peer_ldf(mkpT + off, peer);
  }
}

// One GNN layer, DOUT=32, relu. src = xs (L1) or h (L2-4), dest = h in place.
template <int DIN>
__device__ __forceinline__ void layer32(SM* s, const float* src,
                                        const float* gWs, const float* gWm,
                                        const float* gWk, int par, int tid,
                                        int lane, int wid, uint32_t peer) {
  float* mkpT = s->mkpT[par];
  // stage weights: Ws transposed (scalar); Wm/Wk row-major (vectorized)
  for (int i = tid; i < DIN * 32; i += NT) {
    int d = i >> 5, hh = i & 31;
    s->wsT[d * 32 + hh] = gWs[hh * DIN + d];
  }
  if (DIN == 32) {
    if (tid < 256)
      ((float4*)s->wm)[tid] = ((const float4*)gWm)[tid];
    else if (tid < 512)
      ((float4*)s->wk)[tid - 256] = ((const float4*)gWk)[tid - 256];
  } else {
    if (tid < 64) {
      s->wm[tid] = gWm[tid];
      s->wk[tid] = gWk[tid];
    }
  }
  msgs<DIN>(s, src, mkpT, lane, wid);
  csync();  // mkpT visible cluster-wide; also orders local staging/mmT
  combine_mk<DIN>(s, mkpT, tid, peer);
  __syncthreads();
  // bias GEMMs: thread = (mk, h'-pair); both slots in one d-loop.
  // Table reads coalesced conflict-free; weights warp-uniform broadcasts.
  {
    const int mk = tid & 31, hh2 = tid >> 5;  // hh2 in [0,16)
    float b0 = 0.f, b1 = 0.f, c0 = 0.f, c1 = 0.f;
#pragma unroll
    for (int d = 0; d < DIN; d++) {
      float am = s->mmT[d * TP + mk];
      float ak = s->mkcT[d * TP + mk];
      float wm0 = s->wm[(2 * hh2) * DIN + d];
      float wm1 = s->wm[(2 * hh2 + 1) * DIN + d];
      float wk0 = s->wk[(2 * hh2) * DIN + d];
      float wk1 = s->wk[(2 * hh2 + 1) * DIN + d];
      b0 += wm0 * am;
      b1 += wm1 * am;
      c0 += wk0 * ak;
      c1 += wk1 * ak;
    }
    *(float2*)(s->bm + mk * 34 + 2 * hh2) = make_float2(b0, b1);
    *(float2*)(s->bk + mk * 34 + 2 * hh2) = make_float2(c0, c1);
  }
  __syncthreads();

  // ---- edge GEMM: 2 edges x 32 h' per thread (R3-exact) ----
  const int e0 = 2 * tid, m = e0 >> 5, k0 = e0 & 31;
  ull a0[16], a1[16];
#pragma unroll
  for (int j = 0; j < 16; j++) {
    float2 bmv = *(const float2*)(s->bm + m * 34 + 2 * j);
    float2 b0v = *(const float2*)(s->bk + k0 * 34 + 2 * j);
    float2 b1v = *(const float2*)(s->bk + (k0 + 1) * 34 + 2 * j);
    a0[j] = pk2(bmv.x + b0v.x, bmv.y + b0v.y);
    a1[j] = pk2(bmv.x + b1v.x, bmv.y + b1v.y);
  }
#pragma unroll 4
  for (int d = 0; d < DIN; d++) {
    float2 hv = *(const float2*)(src + d * 1024 + e0);
    ull H0 = pk2(hv.x, hv.x), H1 = pk2(hv.y, hv.y);
    const ulonglong2* wr = (const ulonglong2*)(s->wsT + d * 32);
#pragma unroll
    for (int q = 0; q < 8; q++) {
      ulonglong2 w = wr[q];  // broadcast LDS.128, used directly (no repack)
      fma2(a0[2 * q], H0, w.x);
      fma2(a0[2 * q + 1], H0, w.y);
      fma2(a1[2 * q], H1, w.x);
      fma2(a1[2 * q + 1], H1, w.y);
    }
  }
  // threads touch only their own 2 columns -> in-place is private, no barrier
#pragma unroll
  for (int j = 0; j < 16; j++) {
    float x0, x1, y0, y1;
    upk2(a0[j], x0, x1);
    upk2(a1[j], y0, y1);
    x0 = fmaxf(x0, 0.f); x1 = fmaxf(x1, 0.f);
    y0 = fmaxf(y0, 0.f); y1 = fmaxf(y1, 0.f);
    *(float2*)(s->h + (2 * j) * 1024 + e0) = make_float2(x0, y0);
    *(float2*)(s->h + (2 * j + 1) * 1024 + e0) = make_float2(x1, y1);
  }
  __syncthreads();  // h ready for next layer
}

__global__ void __launch_bounds__(NT, 1) __cluster_dims__(2, 1, 1)
gnn_kernel(Params p) {
  SM* s = (SM*)smem_raw;
  const int tid = threadIdx.x, lane = tid & 31, wid = tid >> 5;
  uint32_t rank;
  asm("mov.u32 %0, %%cluster_ctarank;" : "=r"(rank));
  const uint32_t peer = rank ^ 1u;
  const int sample = blockIdx.x >> 1;

  // stage x -> xs[c][e]
  {
    const float* xg = p.x + (size_t)sample * 4096 + (size_t)rank * 2048;
    float4 v = *(const float4*)(xg + 4 * tid);
    int e0 = 2 * tid;
    s->xs[e0] = v.x; s->xs[e0 + 1] = v.z;
    s->xs[1024 + e0] = v.y; s->xs[1024 + e0 + 1] = v.w;
  }
  __syncthreads();

  // parities: L1:0 L2:1 L3:0 L4:1 L5:0 (overwrite distance 2 => safe)
  layer32<2>(s, s->xs, p.w[0], p.w[1], p.w[2], 0, tid, lane, wid, peer);
  for (int l = 1; l < 4; ++l)
    layer32<32>(s, s->h, p.w[3 * l], p.w[3 * l + 1], p.w[3 * l + 2], l & 1,
                tid, lane, wid, peer);

  // ---- layer 5 (DIN=32, DOUT=2, no relu) + power norm + store ----
  {
    const float* gWs = p.w[12];
    const float* gWm = p.w[13];
    const float* gWk = p.w[14];
    float* mkpT = s->mkpT[0];
    if (tid < 64) {  // Ws^T stride-2; Wm/Wk row-major (2,32) straight copy
      int d = tid >> 1, hh = tid & 1;
      s->wsT[d * 2 + hh] = gWs[hh * 32 + d];
      s->wm[tid] = gWm[tid];
      s->wk[tid] = gWk[tid];
    }
    msgs<32>(s, s->h, mkpT, lane, wid);
    csync();
    combine_mk<32>(s, mkpT, tid, peer);
    __syncthreads();
    if (tid < 32) {  // bias: one mk per thread, both h' in one pass
      float b0 = 0.f, b1 = 0.f, c0 = 0.f, c1 = 0.f;
#pragma unroll
      for (int d = 0; d < 32; d++) {
        float am = s->mmT[d * TP + tid];
        float ak = s->mkcT[d * TP + tid];
        b0 += s->wm[d] * am;
        b1 += s->wm[32 + d] * am;
        c0 += s->wk[d] * ak;
        c1 += s->wk[32 + d] * ak;
      }
      *(float2*)(s->bm + tid * 34) = make_float2(b0, b1);
      *(float2*)(s->bk + tid * 34) = make_float2(c0, c1);
    }
    __syncthreads();

    // 2 edges per thread
    const int e0 = 2 * tid, m = e0 >> 5, k0 = e0 & 31;
    float2 bmv = *(const float2*)(s->bm + m * 34);
    float2 b0v = *(const float2*)(s->bk + k0 * 34);
    float2 b1v = *(const float2*)(s->bk + (k0 + 1) * 34);
    ull a0 = pk2(bmv.x + b0v.x, bmv.y + b0v.y);
    ull a1 = pk2(bmv.x + b1v.x, bmv.y + b1v.y);
#pragma unroll 8
    for (int d = 0; d < 32; d++) {
      float2 hv = *(const float2*)(s->h + d * 1024 + e0);
      ull w = *(const ull*)(s->wsT + d * 2);
      fma2(a0, pk2(hv.x, hv.x), w);
      fma2(a1, pk2(hv.y, hv.y), w);
    }
    float x0, x1, y0, y1;
    upk2(a0, x0, x1);
    upk2(a1, y0, y1);

    // power = sum over whole sample of z^2
    float pl = x0 * x0 + x1 * x1 + y0 * y0 + y1 * y1;
    pl += __shfl_xor_sync(0xffffffffu, pl, 1);
    pl += __shfl_xor_sync(0xffffffffu, pl, 2);
    pl += __shfl_xor_sync(0xffffffffu, pl, 4);
    pl += __shfl_xor_sync(0xffffffffu, pl, 8);
    pl += __shfl_xor_sync(0xffffffffu, pl, 16);
    if (lane == 0) s->red[wid] = pl;
    __syncthreads();
    if (tid == 0) {
      float t = 0.f;
#pragma unroll
      for (int w2 = 0; w2 < NW; w2++) t += s->red[w2];
      s->powslot = t;
    }
    csync();  // both CTAs' powslot ready
    float al = rsqrtf(s->powslot + peer_ldf(&s->powslot, peer));  // PT = 1

    float4 o = make_float4(al * x0, al * x1, al * y0, al * y1);
    *(float4*)(p.out + (size_t)sample * 4096 + (size_t)rank * 2048 + 4 * tid) = o;
    csync();  // keep our smem alive until peer finished its powslot read
  }
}

extern "C" void kernel_launch(void* const* d_in, const int* in_sizes, int n_in,
                              void* d_out, int out_size) {
  Params p;
  p.x = (const float*)d_in[0];
  for (int i = 0; i < 15; i++) p.w[i] = (const float*)d_in[1 + i];
  p.out = (float*)d_out;
  cudaFuncSetAttribute(gnn_kernel, cudaFuncAttributeMaxDynamicSharedMemorySize,
                       (int)sizeof(SM));
  gnn_kernel<<<2048, NT, sizeof(SM)>>>(p);
}